// round 6
// baseline (speedup 1.0000x reference)
#include <cuda_runtime.h>
#include <cstdint>

// Problem constants
#define B_  2
#define S_  2048
#define D_  1024
#define H_  16
#define DK_ 64
#define M_  (B_ * S_)          // 4096 rows for projections
#define BH_ (B_ * H_)          // 32

// ---------------------------------------------------------------------------
// Device scratch (allocation-free rule: __device__ globals)
// ---------------------------------------------------------------------------
__device__ float g_Q[BH_ * S_ * DK_];        // [b,h,s,dk]  16 MB
__device__ float g_K[BH_ * S_ * DK_];        // 16 MB
__device__ float g_V[BH_ * S_ * DK_];        // 16 MB
__device__ float g_Scr[(size_t)BH_ * S_ * S_]; // [b,h,q,k]  512 MiB
__device__ float g_O[M_ * D_];               // merged context [B,S,D] 32 MB

// ---------------------------------------------------------------------------
// Kernel 1/5: C = A[M,1024] @ W[1024,1024]^T + bias
// split: 0/1/2 -> write head-split into g_Q/g_K/g_V ; 3 -> plain into outPlain
// 128x128 tile, BK=8, 256 threads, 8x8 register tile.
// ---------------------------------------------------------------------------
__global__ void __launch_bounds__(256) gemm_xwT_kernel(
    const float* __restrict__ A, const float* __restrict__ W,
    const float* __restrict__ bias, float* __restrict__ outPlain, int split)
{
    __shared__ float As[8][128];
    __shared__ float Ws[8][128];

    const int bm = blockIdx.y, bn = blockIdx.x;
    const int tid = threadIdx.x;
    const int lrow = tid >> 1;           // 0..127
    const int lc4  = (tid & 1) * 4;      // 0 or 4
    const int ty = tid >> 4, tx = tid & 15;

    const float* Ab = A + (size_t)(bm * 128 + lrow) * 1024 + lc4;
    const float* Wb = W + (size_t)(bn * 128 + lrow) * 1024 + lc4;

    float acc[8][8];
#pragma unroll
    for (int i = 0; i < 8; i++)
#pragma unroll
        for (int j = 0; j < 8; j++) acc[i][j] = 0.f;

    for (int kt = 0; kt < 1024; kt += 8) {
        float4 av = *(const float4*)(Ab + kt);
        float4 wv = *(const float4*)(Wb + kt);
        As[lc4 + 0][lrow] = av.x; As[lc4 + 1][lrow] = av.y;
        As[lc4 + 2][lrow] = av.z; As[lc4 + 3][lrow] = av.w;
        Ws[lc4 + 0][lrow] = wv.x; Ws[lc4 + 1][lrow] = wv.y;
        Ws[lc4 + 2][lrow] = wv.z; Ws[lc4 + 3][lrow] = wv.w;
        __syncthreads();
#pragma unroll
        for (int k = 0; k < 8; k++) {
            float4 a0 = *(const float4*)&As[k][ty * 8];
            float4 a1 = *(const float4*)&As[k][ty * 8 + 4];
            float4 b0 = *(const float4*)&Ws[k][tx * 8];
            float4 b1 = *(const float4*)&Ws[k][tx * 8 + 4];
            float a[8] = {a0.x, a0.y, a0.z, a0.w, a1.x, a1.y, a1.z, a1.w};
            float b[8] = {b0.x, b0.y, b0.z, b0.w, b1.x, b1.y, b1.z, b1.w};
#pragma unroll
            for (int i = 0; i < 8; i++)
#pragma unroll
                for (int j = 0; j < 8; j++) acc[i][j] += a[i] * b[j];
        }
        __syncthreads();
    }

    float* Csplit = (split == 0) ? g_Q : (split == 1) ? g_K : g_V;
#pragma unroll
    for (int i = 0; i < 8; i++) {
        int m = bm * 128 + ty * 8 + i;
#pragma unroll
        for (int j = 0; j < 8; j++) {
            int n = bn * 128 + tx * 8 + j;
            float v = acc[i][j] + bias[n];
            if (split < 3) {
                int b = m >> 11, s = m & 2047;
                int h = n >> 6,  dk = n & 63;
                Csplit[(((size_t)(b * H_ + h)) * S_ + s) * DK_ + dk] = v;
            } else {
                outPlain[(size_t)m * D_ + n] = v;
            }
        }
    }
}

// ---------------------------------------------------------------------------
// Kernel 2/5: per (b,h): S[q,k] = (Q K^T)/8 with mask -> g_Scr
// 128x128 tile, K=64 (8 k-steps).
// ---------------------------------------------------------------------------
__global__ void __launch_bounds__(256) scores_kernel(const int* __restrict__ mask)
{
    const int bh = blockIdx.z;
    const float* Qb = g_Q + (size_t)bh * S_ * DK_;
    const float* Kb = g_K + (size_t)bh * S_ * DK_;
    float* Sb = g_Scr + (size_t)bh * S_ * S_;

    __shared__ float Qs[8][128];
    __shared__ float Ks[8][128];

    const int bm = blockIdx.y, bn = blockIdx.x;
    const int tid = threadIdx.x;
    const int lrow = tid >> 1;
    const int lc4  = (tid & 1) * 4;
    const int ty = tid >> 4, tx = tid & 15;

    float acc[8][8];
#pragma unroll
    for (int i = 0; i < 8; i++)
#pragma unroll
        for (int j = 0; j < 8; j++) acc[i][j] = 0.f;

    for (int kt = 0; kt < 64; kt += 8) {
        float4 qv = *(const float4*)(Qb + (size_t)(bm * 128 + lrow) * 64 + kt + lc4);
        float4 kv = *(const float4*)(Kb + (size_t)(bn * 128 + lrow) * 64 + kt + lc4);
        Qs[lc4 + 0][lrow] = qv.x; Qs[lc4 + 1][lrow] = qv.y;
        Qs[lc4 + 2][lrow] = qv.z; Qs[lc4 + 3][lrow] = qv.w;
        Ks[lc4 + 0][lrow] = kv.x; Ks[lc4 + 1][lrow] = kv.y;
        Ks[lc4 + 2][lrow] = kv.z; Ks[lc4 + 3][lrow] = kv.w;
        __syncthreads();
#pragma unroll
        for (int k = 0; k < 8; k++) {
            float4 a0 = *(const float4*)&Qs[k][ty * 8];
            float4 a1 = *(const float4*)&Qs[k][ty * 8 + 4];
            float4 b0 = *(const float4*)&Ks[k][tx * 8];
            float4 b1 = *(const float4*)&Ks[k][tx * 8 + 4];
            float a[8] = {a0.x, a0.y, a0.z, a0.w, a1.x, a1.y, a1.z, a1.w};
            float b[8] = {b0.x, b0.y, b0.z, b0.w, b1.x, b1.y, b1.z, b1.w};
#pragma unroll
            for (int i = 0; i < 8; i++)
#pragma unroll
                for (int j = 0; j < 8; j++) acc[i][j] += a[i] * b[j];
        }
        __syncthreads();
    }

#pragma unroll
    for (int i = 0; i < 8; i++) {
        int q = bm * 128 + ty * 8 + i;
#pragma unroll
        for (int j = 0; j < 8; j++) {
            int k = bn * 128 + tx * 8 + j;
            int mk = mask[(size_t)q * S_ + k];
            Sb[(size_t)q * S_ + k] = mk ? acc[i][j] * 0.125f : -1e9f;
        }
    }
}

// ---------------------------------------------------------------------------
// Kernel 3/5: softmax over the HEADS axis (axis=1 of [B,H,S,S]).
// One thread per (b,q,k); 16 head values live in registers.
// Fully masked columns (all -1e9) correctly become 1/16 each via max-subtract.
// ---------------------------------------------------------------------------
__global__ void __launch_bounds__(256) softmax_heads_kernel()
{
    size_t idx = (size_t)blockIdx.x * blockDim.x + threadIdx.x;
    const size_t SS = (size_t)S_ * S_;
    if (idx >= (size_t)B_ * SS) return;
    size_t b = idx / SS;
    size_t r = idx - b * SS;       // q*S + k
    size_t base = b * H_ * SS + r;

    float v[H_];
    float mx = -3.4e38f;
#pragma unroll
    for (int h = 0; h < H_; h++) {
        v[h] = g_Scr[base + (size_t)h * SS];
        mx = fmaxf(mx, v[h]);
    }
    float sum = 0.f;
#pragma unroll
    for (int h = 0; h < H_; h++) {
        v[h] = __expf(v[h] - mx);
        sum += v[h];
    }
    float inv = 1.f / sum;
#pragma unroll
    for (int h = 0; h < H_; h++) {
        g_Scr[base + (size_t)h * SS] = v[h] * inv;
    }
}

// ---------------------------------------------------------------------------
// Kernel 4/5: per (b,h): O[q,dk] = P[q,:] @ V[:,dk], written merged [B,S,D].
// BM=128, BN=64, BK=16; 256 threads; 8x4 register tile.
// ---------------------------------------------------------------------------
__global__ void __launch_bounds__(256) av_kernel()
{
    const int bh = blockIdx.y;
    const int b = bh >> 4, h = bh & 15;
    const float* Pb = g_Scr + (size_t)bh * S_ * S_;
    const float* Vb = g_V + (size_t)bh * S_ * DK_;
    const int bm = blockIdx.x;

    __shared__ float Ps[16][128];
    __shared__ float Vs[16][64];

    const int tid = threadIdx.x;
    const int ty = tid >> 4, tx = tid & 15;

    float acc[8][4];
#pragma unroll
    for (int i = 0; i < 8; i++)
#pragma unroll
        for (int j = 0; j < 4; j++) acc[i][j] = 0.f;

    for (int kt = 0; kt < S_; kt += 16) {
#pragma unroll
        for (int u = 0; u < 2; u++) {
            int f4 = tid + u * 256;          // 0..511
            int pr = f4 >> 2;                // 0..127
            int pc4 = (f4 & 3) * 4;          // 0,4,8,12
            float4 pv = *(const float4*)(Pb + (size_t)(bm * 128 + pr) * S_ + kt + pc4);
            Ps[pc4 + 0][pr] = pv.x; Ps[pc4 + 1][pr] = pv.y;
            Ps[pc4 + 2][pr] = pv.z; Ps[pc4 + 3][pr] = pv.w;
        }
        {
            int vr = tid >> 4;               // 0..15 (k)
            int vc4 = (tid & 15) * 4;        // 0..60
            float4 vv = *(const float4*)(Vb + (size_t)(kt + vr) * DK_ + vc4);
            *(float4*)&Vs[vr][vc4] = vv;
        }
        __syncthreads();
#pragma unroll
        for (int k = 0; k < 16; k++) {
            float4 a0 = *(const float4*)&Ps[k][ty * 8];
            float4 a1 = *(const float4*)&Ps[k][ty * 8 + 4];
            float4 b0 = *(const float4*)&Vs[k][tx * 4];
            float a[8] = {a0.x, a0.y, a0.z, a0.w, a1.x, a1.y, a1.z, a1.w};
            float bb[4] = {b0.x, b0.y, b0.z, b0.w};
#pragma unroll
            for (int i = 0; i < 8; i++)
#pragma unroll
                for (int j = 0; j < 4; j++) acc[i][j] += a[i] * bb[j];
        }
        __syncthreads();
    }

#pragma unroll
    for (int i = 0; i < 8; i++) {
        int q = bm * 128 + ty * 8 + i;
#pragma unroll
        for (int j = 0; j < 4; j++) {
            int n = tx * 4 + j;
            g_O[((size_t)b * S_ + q) * D_ + h * DK_ + n] = acc[i][j];
        }
    }
}

// ---------------------------------------------------------------------------
// Launch
// ---------------------------------------------------------------------------
extern "C" void kernel_launch(void* const* d_in, const int* in_sizes, int n_in,
                              void* d_out, int out_size)
{
    const float* q    = (const float*)d_in[0];
    const float* k    = (const float*)d_in[1];
    const float* v    = (const float*)d_in[2];
    const int*   mask = (const int*)  d_in[3];
    const float* wq_w = (const float*)d_in[4];
    const float* wq_b = (const float*)d_in[5];
    const float* wk_w = (const float*)d_in[6];
    const float* wk_b = (const float*)d_in[7];
    const float* wv_w = (const float*)d_in[8];
    const float* wv_b = (const float*)d_in[9];
    const float* wo_w = (const float*)d_in[10];
    const float* wo_b = (const float*)d_in[11];
    float* out = (float*)d_out;

    // resolve g_O address for the final GEMM's A operand
    float* gO_ptr = nullptr;
    cudaGetSymbolAddress((void**)&gO_ptr, g_O);

    dim3 gproj(D_ / 128, M_ / 128);            // (8, 32)
    gemm_xwT_kernel<<<gproj, 256>>>(q, wq_w, wq_b, nullptr, 0);
    gemm_xwT_kernel<<<gproj, 256>>>(k, wk_w, wk_b, nullptr, 1);
    gemm_xwT_kernel<<<gproj, 256>>>(v, wv_w, wv_b, nullptr, 2);

    dim3 gsc(S_ / 128, S_ / 128, BH_);         // (16, 16, 32)
    scores_kernel<<<gsc, 256>>>(mask);

    size_t nsm = (size_t)B_ * S_ * S_;         // 8,388,608
    softmax_heads_kernel<<<(unsigned)((nsm + 255) / 256), 256>>>();

    dim3 gav(S_ / 128, BH_);                   // (16, 32)
    av_kernel<<<gav, 256>>>();

    gemm_xwT_kernel<<<gproj, 256>>>(gO_ptr, wo_w, wo_b, out, 3);
}

// round 7
// speedup vs baseline: 1.0004x; 1.0004x over previous
#include <cuda_runtime.h>
#include <cstdint>

// Problem constants
#define B_  2
#define S_  2048
#define D_  1024
#define H_  16
#define DK_ 64
#define M_  (B_ * S_)          // 4096 rows for projections
#define BH_ (B_ * H_)          // 32

// ---------------------------------------------------------------------------
// Device scratch (allocation-free rule: __device__ globals)
// ---------------------------------------------------------------------------
__device__ float g_Q[BH_ * S_ * DK_];        // [b,h,s,dk]  16 MB
__device__ float g_K[BH_ * S_ * DK_];        // 16 MB
__device__ float g_V[BH_ * S_ * DK_];        // 16 MB
__device__ float g_Scr[(size_t)BH_ * S_ * S_]; // [b,h,q,k]  512 MiB
__device__ float g_O[M_ * D_];               // merged context [B,S,D] 32 MB

// ---------------------------------------------------------------------------
// Kernel 1/5: C = A[M,1024] @ W[1024,1024]^T + bias
// split: 0/1/2 -> write head-split into g_Q/g_K/g_V ; 3 -> plain into outPlain
// 128x128 tile, BK=8, 256 threads, 8x8 register tile.
// ---------------------------------------------------------------------------
__global__ void __launch_bounds__(256) gemm_xwT_kernel(
    const float* __restrict__ A, const float* __restrict__ W,
    const float* __restrict__ bias, float* __restrict__ outPlain, int split)
{
    __shared__ float As[8][128];
    __shared__ float Ws[8][128];

    const int bm = blockIdx.y, bn = blockIdx.x;
    const int tid = threadIdx.x;
    const int lrow = tid >> 1;           // 0..127
    const int lc4  = (tid & 1) * 4;      // 0 or 4
    const int ty = tid >> 4, tx = tid & 15;

    const float* Ab = A + (size_t)(bm * 128 + lrow) * 1024 + lc4;
    const float* Wb = W + (size_t)(bn * 128 + lrow) * 1024 + lc4;

    float acc[8][8];
#pragma unroll
    for (int i = 0; i < 8; i++)
#pragma unroll
        for (int j = 0; j < 8; j++) acc[i][j] = 0.f;

    for (int kt = 0; kt < 1024; kt += 8) {
        float4 av = *(const float4*)(Ab + kt);
        float4 wv = *(const float4*)(Wb + kt);
        As[lc4 + 0][lrow] = av.x; As[lc4 + 1][lrow] = av.y;
        As[lc4 + 2][lrow] = av.z; As[lc4 + 3][lrow] = av.w;
        Ws[lc4 + 0][lrow] = wv.x; Ws[lc4 + 1][lrow] = wv.y;
        Ws[lc4 + 2][lrow] = wv.z; Ws[lc4 + 3][lrow] = wv.w;
        __syncthreads();
#pragma unroll
        for (int k = 0; k < 8; k++) {
            float4 a0 = *(const float4*)&As[k][ty * 8];
            float4 a1 = *(const float4*)&As[k][ty * 8 + 4];
            float4 b0 = *(const float4*)&Ws[k][tx * 8];
            float4 b1 = *(const float4*)&Ws[k][tx * 8 + 4];
            float a[8] = {a0.x, a0.y, a0.z, a0.w, a1.x, a1.y, a1.z, a1.w};
            float b[8] = {b0.x, b0.y, b0.z, b0.w, b1.x, b1.y, b1.z, b1.w};
#pragma unroll
            for (int i = 0; i < 8; i++)
#pragma unroll
                for (int j = 0; j < 8; j++) acc[i][j] += a[i] * b[j];
        }
        __syncthreads();
    }

    float* Csplit = (split == 0) ? g_Q : (split == 1) ? g_K : g_V;
#pragma unroll
    for (int i = 0; i < 8; i++) {
        int m = bm * 128 + ty * 8 + i;
#pragma unroll
        for (int j = 0; j < 8; j++) {
            int n = bn * 128 + tx * 8 + j;
            float v = acc[i][j] + bias[n];
            if (split < 3) {
                int b = m >> 11, s = m & 2047;
                int h = n >> 6,  dk = n & 63;
                Csplit[(((size_t)(b * H_ + h)) * S_ + s) * DK_ + dk] = v;
            } else {
                outPlain[(size_t)m * D_ + n] = v;
            }
        }
    }
}

// ---------------------------------------------------------------------------
// Kernel 2/5: per (b,h): S[q,k] = (Q K^T)/8 with mask -> g_Scr
// 128x128 tile, K=64 (8 k-steps).
// ---------------------------------------------------------------------------
__global__ void __launch_bounds__(256) scores_kernel(const int* __restrict__ mask)
{
    const int bh = blockIdx.z;
    const float* Qb = g_Q + (size_t)bh * S_ * DK_;
    const float* Kb = g_K + (size_t)bh * S_ * DK_;
    float* Sb = g_Scr + (size_t)bh * S_ * S_;

    __shared__ float Qs[8][128];
    __shared__ float Ks[8][128];

    const int bm = blockIdx.y, bn = blockIdx.x;
    const int tid = threadIdx.x;
    const int lrow = tid >> 1;
    const int lc4  = (tid & 1) * 4;
    const int ty = tid >> 4, tx = tid & 15;

    float acc[8][8];
#pragma unroll
    for (int i = 0; i < 8; i++)
#pragma unroll
        for (int j = 0; j < 8; j++) acc[i][j] = 0.f;

    for (int kt = 0; kt < 64; kt += 8) {
        float4 qv = *(const float4*)(Qb + (size_t)(bm * 128 + lrow) * 64 + kt + lc4);
        float4 kv = *(const float4*)(Kb + (size_t)(bn * 128 + lrow) * 64 + kt + lc4);
        Qs[lc4 + 0][lrow] = qv.x; Qs[lc4 + 1][lrow] = qv.y;
        Qs[lc4 + 2][lrow] = qv.z; Qs[lc4 + 3][lrow] = qv.w;
        Ks[lc4 + 0][lrow] = kv.x; Ks[lc4 + 1][lrow] = kv.y;
        Ks[lc4 + 2][lrow] = kv.z; Ks[lc4 + 3][lrow] = kv.w;
        __syncthreads();
#pragma unroll
        for (int k = 0; k < 8; k++) {
            float4 a0 = *(const float4*)&Qs[k][ty * 8];
            float4 a1 = *(const float4*)&Qs[k][ty * 8 + 4];
            float4 b0 = *(const float4*)&Ks[k][tx * 8];
            float4 b1 = *(const float4*)&Ks[k][tx * 8 + 4];
            float a[8] = {a0.x, a0.y, a0.z, a0.w, a1.x, a1.y, a1.z, a1.w};
            float b[8] = {b0.x, b0.y, b0.z, b0.w, b1.x, b1.y, b1.z, b1.w};
#pragma unroll
            for (int i = 0; i < 8; i++)
#pragma unroll
                for (int j = 0; j < 8; j++) acc[i][j] += a[i] * b[j];
        }
        __syncthreads();
    }

#pragma unroll
    for (int i = 0; i < 8; i++) {
        int q = bm * 128 + ty * 8 + i;
#pragma unroll
        for (int j = 0; j < 8; j++) {
            int k = bn * 128 + tx * 8 + j;
            int mk = mask[(size_t)q * S_ + k];
            Sb[(size_t)q * S_ + k] = mk ? acc[i][j] * 0.125f : -1e9f;
        }
    }
}

// ---------------------------------------------------------------------------
// Kernel 3/5: softmax over the HEADS axis (axis=1 of [B,H,S,S]).
// One thread per (b,q,k); 16 head values live in registers.
// Fully masked columns (all -1e9) correctly become 1/16 each via max-subtract.
// ---------------------------------------------------------------------------
__global__ void __launch_bounds__(256) softmax_heads_kernel()
{
    size_t idx = (size_t)blockIdx.x * blockDim.x + threadIdx.x;
    const size_t SS = (size_t)S_ * S_;
    if (idx >= (size_t)B_ * SS) return;
    size_t b = idx / SS;
    size_t r = idx - b * SS;       // q*S + k
    size_t base = b * H_ * SS + r;

    float v[H_];
    float mx = -3.4e38f;
#pragma unroll
    for (int h = 0; h < H_; h++) {
        v[h] = g_Scr[base + (size_t)h * SS];
        mx = fmaxf(mx, v[h]);
    }
    float sum = 0.f;
#pragma unroll
    for (int h = 0; h < H_; h++) {
        v[h] = __expf(v[h] - mx);
        sum += v[h];
    }
    float inv = 1.f / sum;
#pragma unroll
    for (int h = 0; h < H_; h++) {
        g_Scr[base + (size_t)h * SS] = v[h] * inv;
    }
}

// ---------------------------------------------------------------------------
// Kernel 4/5: per (b,h): O[q,dk] = P[q,:] @ V[:,dk], written merged [B,S,D].
// BM=128, BN=64, BK=16; 256 threads; 8x4 register tile.
// ---------------------------------------------------------------------------
__global__ void __launch_bounds__(256) av_kernel()
{
    const int bh = blockIdx.y;
    const int b = bh >> 4, h = bh & 15;
    const float* Pb = g_Scr + (size_t)bh * S_ * S_;
    const float* Vb = g_V + (size_t)bh * S_ * DK_;
    const int bm = blockIdx.x;

    __shared__ float Ps[16][128];
    __shared__ float Vs[16][64];

    const int tid = threadIdx.x;
    const int ty = tid >> 4, tx = tid & 15;

    float acc[8][4];
#pragma unroll
    for (int i = 0; i < 8; i++)
#pragma unroll
        for (int j = 0; j < 4; j++) acc[i][j] = 0.f;

    for (int kt = 0; kt < S_; kt += 16) {
#pragma unroll
        for (int u = 0; u < 2; u++) {
            int f4 = tid + u * 256;          // 0..511
            int pr = f4 >> 2;                // 0..127
            int pc4 = (f4 & 3) * 4;          // 0,4,8,12
            float4 pv = *(const float4*)(Pb + (size_t)(bm * 128 + pr) * S_ + kt + pc4);
            Ps[pc4 + 0][pr] = pv.x; Ps[pc4 + 1][pr] = pv.y;
            Ps[pc4 + 2][pr] = pv.z; Ps[pc4 + 3][pr] = pv.w;
        }
        {
            int vr = tid >> 4;               // 0..15 (k)
            int vc4 = (tid & 15) * 4;        // 0..60
            float4 vv = *(const float4*)(Vb + (size_t)(kt + vr) * DK_ + vc4);
            *(float4*)&Vs[vr][vc4] = vv;
        }
        __syncthreads();
#pragma unroll
        for (int k = 0; k < 16; k++) {
            float4 a0 = *(const float4*)&Ps[k][ty * 8];
            float4 a1 = *(const float4*)&Ps[k][ty * 8 + 4];
            float4 b0 = *(const float4*)&Vs[k][tx * 4];
            float a[8] = {a0.x, a0.y, a0.z, a0.w, a1.x, a1.y, a1.z, a1.w};
            float bb[4] = {b0.x, b0.y, b0.z, b0.w};
#pragma unroll
            for (int i = 0; i < 8; i++)
#pragma unroll
                for (int j = 0; j < 4; j++) acc[i][j] += a[i] * bb[j];
        }
        __syncthreads();
    }

#pragma unroll
    for (int i = 0; i < 8; i++) {
        int q = bm * 128 + ty * 8 + i;
#pragma unroll
        for (int j = 0; j < 4; j++) {
            int n = tx * 4 + j;
            g_O[((size_t)b * S_ + q) * D_ + h * DK_ + n] = acc[i][j];
        }
    }
}

// ---------------------------------------------------------------------------
// Launch
// ---------------------------------------------------------------------------
extern "C" void kernel_launch(void* const* d_in, const int* in_sizes, int n_in,
                              void* d_out, int out_size)
{
    const float* q    = (const float*)d_in[0];
    const float* k    = (const float*)d_in[1];
    const float* v    = (const float*)d_in[2];
    const int*   mask = (const int*)  d_in[3];
    const float* wq_w = (const float*)d_in[4];
    const float* wq_b = (const float*)d_in[5];
    const float* wk_w = (const float*)d_in[6];
    const float* wk_b = (const float*)d_in[7];
    const float* wv_w = (const float*)d_in[8];
    const float* wv_b = (const float*)d_in[9];
    const float* wo_w = (const float*)d_in[10];
    const float* wo_b = (const float*)d_in[11];
    float* out = (float*)d_out;

    // resolve g_O address for the final GEMM's A operand
    float* gO_ptr = nullptr;
    cudaGetSymbolAddress((void**)&gO_ptr, g_O);

    dim3 gproj(D_ / 128, M_ / 128);            // (8, 32)
    gemm_xwT_kernel<<<gproj, 256>>>(q, wq_w, wq_b, nullptr, 0);
    gemm_xwT_kernel<<<gproj, 256>>>(k, wk_w, wk_b, nullptr, 1);
    gemm_xwT_kernel<<<gproj, 256>>>(v, wv_w, wv_b, nullptr, 2);

    dim3 gsc(S_ / 128, S_ / 128, BH_);         // (16, 16, 32)
    scores_kernel<<<gsc, 256>>>(mask);

    size_t nsm = (size_t)B_ * S_ * S_;         // 8,388,608
    softmax_heads_kernel<<<(unsigned)((nsm + 255) / 256), 256>>>();

    dim3 gav(S_ / 128, BH_);                   // (16, 32)
    av_kernel<<<gav, 256>>>();

    gemm_xwT_kernel<<<gproj, 256>>>(gO_ptr, wo_w, wo_b, out, 3);
}

// round 10
// speedup vs baseline: 1.8773x; 1.8766x over previous
#include <cuda_runtime.h>
#include <cuda_fp16.h>
#include <cstdint>

#define SSZ 4194304ull   // S*S

// ---------------- device scratch ----------------
__device__ __half g_Xh[12582912], g_Xl[12582912];   // q,k,v split [3][4096,1024]
__device__ __half g_Wh[4194304],  g_Wl[4194304];    // wq,wk,wv,wo split [4][1024,1024]
__device__ __half g_Qh[4194304],  g_Ql[4194304];    // [bh,s,64]
__device__ __half g_Kh[4194304],  g_Kl[4194304];    // [bh,s,64]
__device__ __half g_Vt[4194304];                    // V transposed [bh,64,s] single fp16
__device__ float  g_Suf[32768];                     // [bh][16][64] suffix tile sums
__device__ float  g_Scr[134217728];                 // scores fp32 [bh,q,k] lower tiles
__device__ __half g_P16[134217728];                 // probs fp16 [bh,q,k] lower tiles
__device__ __half g_Oh[4194304],  g_Ol[4194304];    // context split [4096,1024]

__device__ __forceinline__ void mma16816(float* c, const uint32_t* a, uint32_t b0, uint32_t b1) {
    asm volatile(
        "mma.sync.aligned.m16n8k16.row.col.f32.f16.f16.f32 "
        "{%0,%1,%2,%3}, {%4,%5,%6,%7}, {%8,%9}, {%0,%1,%2,%3};"
        : "+f"(c[0]), "+f"(c[1]), "+f"(c[2]), "+f"(c[3])
        : "r"(a[0]), "r"(a[1]), "r"(a[2]), "r"(a[3]), "r"(b0), "r"(b1));
}

// ---------------- fp32 -> hi/lo fp16 split ----------------
__global__ void __launch_bounds__(256) cvt_split(const float* __restrict__ src, int slot) {
    int i = blockIdx.x * 256 + threadIdx.x;
    __half* H = (slot < 3) ? g_Xh + (size_t)slot * 4194304ull : g_Wh + (size_t)(slot - 3) * 1048576ull;
    __half* L = (slot < 3) ? g_Xl + (size_t)slot * 4194304ull : g_Wl + (size_t)(slot - 3) * 1048576ull;
    float4 x = reinterpret_cast<const float4*>(src)[i];
    __half h0 = __float2half_rn(x.x), h1 = __float2half_rn(x.y);
    __half h2 = __float2half_rn(x.z), h3 = __float2half_rn(x.w);
    uint2 oh, ol;
    oh.x = (uint32_t)__half_as_ushort(h0) | ((uint32_t)__half_as_ushort(h1) << 16);
    oh.y = (uint32_t)__half_as_ushort(h2) | ((uint32_t)__half_as_ushort(h3) << 16);
    ol.x = (uint32_t)__half_as_ushort(__float2half_rn(x.x - __half2float(h0))) |
           ((uint32_t)__half_as_ushort(__float2half_rn(x.y - __half2float(h1))) << 16);
    ol.y = (uint32_t)__half_as_ushort(__float2half_rn(x.z - __half2float(h2))) |
           ((uint32_t)__half_as_ushort(__float2half_rn(x.w - __half2float(h3))) << 16);
    reinterpret_cast<uint2*>(H)[i] = oh;
    reinterpret_cast<uint2*>(L)[i] = ol;
}

// ---------------- generic HMMA GEMM (C = A . B^T) ----------------
// MODE 0/1: X.W^T+b -> Q/K head-split hi/lo.  MODE 2: -> Vt (single fp16, transposed).
// MODE 3: O.Wo^T+b -> fp32 out.  MODE 4: Q.K^T/8 lower tiles -> g_Scr fp32.
// MODE 5: P.V (k-tiles<=bm) + (1/16)*suffix -> g_Oh/g_Ol.
template <int MODE>
__global__ void __launch_bounds__(256, 2) gemm_mma(const float* __restrict__ bias,
                                                   float* __restrict__ out32) {
    constexpr int NT  = (MODE == 5) ? 64 : 128;   // N tile
    constexpr int WNN = NT / 32;                  // warps along n
    constexpr int RW  = (WNN == 4) ? 64 : 32;     // rows per warp
    constexpr int MI  = RW / 16;

    const int bn = blockIdx.x, bm = blockIdx.y, bh = blockIdx.z;
    if (MODE == 4 && bn > bm) return;

    __shared__ __align__(16) __half sS[2][128][72];

    const int tid = threadIdx.x, lane = tid & 31, wid = tid >> 5;
    const int g = lane >> 2, t = lane & 3;
    const int wn = wid % WNN, wm = wid / WNN;

    float acc[MI][4][4];
#pragma unroll
    for (int mi = 0; mi < MI; mi++)
#pragma unroll
        for (int ni = 0; ni < 4; ni++)
#pragma unroll
            for (int j = 0; j < 4; j++) acc[mi][ni][j] = 0.f;

    const __half *Ahi = nullptr, *Alo = nullptr, *Bhi = nullptr, *Blo = nullptr;
    int lda, ldb, NCH, arow0 = bm * 128, brow0 = bn * NT;
    if (MODE == 0) { Ahi = g_Xh;              Alo = g_Xl;              Bhi = g_Wh;              Blo = g_Wl;              lda = ldb = 1024; NCH = 48; }
    if (MODE == 1) { Ahi = g_Xh + 4194304ull; Alo = g_Xl + 4194304ull; Bhi = g_Wh + 1048576ull; Blo = g_Wl + 1048576ull; lda = ldb = 1024; NCH = 48; }
    if (MODE == 2) { Ahi = g_Xh + 8388608ull; Alo = g_Xl + 8388608ull; Bhi = g_Wh + 2097152ull; Blo = g_Wl + 2097152ull; lda = ldb = 1024; NCH = 48; }
    if (MODE == 3) { Ahi = g_Oh;              Alo = g_Ol;              Bhi = g_Wh + 3145728ull; Blo = g_Wl + 3145728ull; lda = ldb = 1024; NCH = 48; }
    if (MODE == 4) { size_t o = (size_t)bh * 131072ull;
                     Ahi = g_Qh + o; Alo = g_Ql + o; Bhi = g_Kh + o; Blo = g_Kl + o;
                     lda = ldb = 64; NCH = 3; }
    if (MODE == 5) { Ahi = g_P16 + (size_t)bh * SSZ; Bhi = g_Vt + (size_t)bh * 131072ull;
                     lda = 2048; ldb = 2048; NCH = 2 * (bm + 1); brow0 = 0; }

    for (int c = 0; c < NCH; c++) {
        const __half *ap, *bp; int ko;
        if (MODE <= 3)      { int seg = c >> 4; ko = (c & 15) * 64;
                              ap = (seg == 1) ? Alo : Ahi; bp = (seg == 2) ? Blo : Bhi; }
        else if (MODE == 4) { ap = (c == 1) ? Alo : Ahi; bp = (c == 2) ? Blo : Bhi; ko = 0; }
        else                { ap = Ahi; bp = Bhi; ko = c * 64; }

        for (int i = tid; i < 128 * 8; i += 256) {
            int r = i >> 3, c8 = (i & 7) << 3;
            *(uint4*)&sS[0][r][c8] = *(const uint4*)(ap + (size_t)(arow0 + r) * lda + ko + c8);
        }
        for (int i = tid; i < NT * 8; i += 256) {
            int r = i >> 3, c8 = (i & 7) << 3;
            *(uint4*)&sS[1][r][c8] = *(const uint4*)(bp + (size_t)(brow0 + r) * ldb + ko + c8);
        }
        __syncthreads();
#pragma unroll
        for (int kk = 0; kk < 4; kk++) {
            uint32_t af[MI][4];
#pragma unroll
            for (int mi = 0; mi < MI; mi++) {
                int rb = wm * RW + mi * 16;
                af[mi][0] = *(const uint32_t*)&sS[0][rb + g][kk * 16 + 2 * t];
                af[mi][1] = *(const uint32_t*)&sS[0][rb + g + 8][kk * 16 + 2 * t];
                af[mi][2] = *(const uint32_t*)&sS[0][rb + g][kk * 16 + 2 * t + 8];
                af[mi][3] = *(const uint32_t*)&sS[0][rb + g + 8][kk * 16 + 2 * t + 8];
            }
#pragma unroll
            for (int ni = 0; ni < 4; ni++) {
                int nb = wn * 32 + ni * 8 + g;
                uint32_t b0 = *(const uint32_t*)&sS[1][nb][kk * 16 + 2 * t];
                uint32_t b1 = *(const uint32_t*)&sS[1][nb][kk * 16 + 2 * t + 8];
#pragma unroll
                for (int mi = 0; mi < MI; mi++) mma16816(acc[mi][ni], af[mi], b0, b1);
            }
        }
        __syncthreads();
    }

    // bias (modes 0-3)
    if (MODE <= 3) {
#pragma unroll
        for (int ni = 0; ni < 4; ni++) {
            int col = bn * 128 + wn * 32 + ni * 8 + 2 * t;
            float2 bv = *(const float2*)&bias[col];
#pragma unroll
            for (int mi = 0; mi < MI; mi++) {
                acc[mi][ni][0] += bv.x; acc[mi][ni][1] += bv.y;
                acc[mi][ni][2] += bv.x; acc[mi][ni][3] += bv.y;
            }
        }
    }
    if (MODE == 5) {  // + (1/16) * suffix of V tiles > bm
#pragma unroll
        for (int ni = 0; ni < 4; ni++) {
            int dk = wn * 32 + ni * 8 + 2 * t;
            float2 sv = *(const float2*)&g_Suf[((size_t)bh * 16 + bm) * 64 + dk];
#pragma unroll
            for (int mi = 0; mi < MI; mi++) {
                acc[mi][ni][0] += 0.0625f * sv.x; acc[mi][ni][1] += 0.0625f * sv.y;
                acc[mi][ni][2] += 0.0625f * sv.x; acc[mi][ni][3] += 0.0625f * sv.y;
            }
        }
    }

    if (MODE == 3) {
#pragma unroll
        for (int mi = 0; mi < MI; mi++)
#pragma unroll
            for (int ni = 0; ni < 4; ni++) {
                int r0 = bm * 128 + wm * RW + mi * 16 + g;
                int cl = bn * 128 + wn * 32 + ni * 8 + 2 * t;
                *(float2*)&out32[(size_t)r0 * 1024 + cl]       = make_float2(acc[mi][ni][0], acc[mi][ni][1]);
                *(float2*)&out32[(size_t)(r0 + 8) * 1024 + cl] = make_float2(acc[mi][ni][2], acc[mi][ni][3]);
            }
        return;
    }
    if (MODE == 4) {
        float* Sd = g_Scr + (size_t)bh * SSZ;
#pragma unroll
        for (int mi = 0; mi < MI; mi++)
#pragma unroll
            for (int ni = 0; ni < 4; ni++) {
                int q0 = bm * 128 + wm * RW + mi * 16 + g;
                int cl = bn * 128 + wn * 32 + ni * 8 + 2 * t;
                *(float2*)&Sd[(size_t)q0 * 2048 + cl]       = make_float2(acc[mi][ni][0] * 0.125f, acc[mi][ni][1] * 0.125f);
                *(float2*)&Sd[(size_t)(q0 + 8) * 2048 + cl] = make_float2(acc[mi][ni][2] * 0.125f, acc[mi][ni][3] * 0.125f);
            }
        return;
    }

    // bounce-buffer epilogues (smem reuse)
    __half* bb = (__half*)sS;  // pitch 136 halves
    const int NPASS = (MODE == 2) ? 1 : 2;
    for (int pass = 0; pass < NPASS; pass++) {
        __syncthreads();
#pragma unroll
        for (int mi = 0; mi < MI; mi++)
#pragma unroll
            for (int ni = 0; ni < 4; ni++) {
                int r0 = wm * RW + mi * 16 + g;
                int cl = wn * 32 + ni * 8 + 2 * t;
                float v0 = acc[mi][ni][0], v1 = acc[mi][ni][1];
                float v2 = acc[mi][ni][2], v3 = acc[mi][ni][3];
                if (pass == 1) {
                    v0 -= __half2float(__float2half_rn(v0));
                    v1 -= __half2float(__float2half_rn(v1));
                    v2 -= __half2float(__float2half_rn(v2));
                    v3 -= __half2float(__float2half_rn(v3));
                }
                *(__half2*)&bb[r0 * 136 + cl]       = __floats2half2_rn(v0, v1);
                *(__half2*)&bb[(r0 + 8) * 136 + cl] = __floats2half2_rn(v2, v3);
            }
        __syncthreads();
        if (MODE <= 1) {
            __half* D = pass ? (MODE ? g_Kl : g_Ql) : (MODE ? g_Kh : g_Qh);
            for (int i = tid; i < 2048; i += 256) {
                int r = i >> 4, c8 = (i & 15) << 3;
                int m = bm * 128 + r, n = bn * 128 + c8;
                size_t dst = ((size_t)((m >> 11) * 16 + (n >> 6)) * 2048 + (m & 2047)) * 64 + (n & 63);
                *(uint4*)&D[dst] = *(const uint4*)&bb[r * 136 + c8];
            }
        } else if (MODE == 5) {
            __half* D = pass ? g_Ol : g_Oh;
            for (int i = tid; i < 1024; i += 256) {
                int r = i >> 3, c8 = (i & 7) << 3;
                size_t dst = ((size_t)(bh >> 4) * 2048 + bm * 128 + r) * 1024 + (bh & 15) * 64 + c8;
                *(uint4*)&D[dst] = *(const uint4*)&bb[r * 136 + c8];
            }
        } else {  // MODE 2: transposed store -> g_Vt
            for (int i = tid; i < 2048; i += 256) {
                int nn = i >> 4, s8 = (i & 15) << 3;
                int n = bn * 128 + nn;
                int b2 = (bm * 128) >> 11, h2 = n >> 6, dk = n & 63;
                union { uint4 q; ushort u[8]; } pk;
#pragma unroll
                for (int j = 0; j < 8; j++)
                    pk.u[j] = __half_as_ushort(bb[(s8 + j) * 136 + nn]);
                size_t dst = ((size_t)(b2 * 16 + h2) * 64 + dk) * 2048 + ((bm * 128) & 2047) + s8;
                *(uint4*)&g_Vt[dst] = pk.q;
            }
        }
    }
}

// ---------------- suffix tile sums of V ----------------
__global__ void __launch_bounds__(256) suffix_k() {
    __shared__ float pts[16][64];
    int bh = blockIdx.x, tid = threadIdx.x, dk = tid & 63, p = tid >> 6;
    for (int tt = 0; tt < 4; tt++) {
        int tt2 = p * 4 + tt;
        const __half* row = g_Vt + ((size_t)bh * 64 + dk) * 2048 + tt2 * 128;
        float s = 0.f;
        for (int j = 0; j < 128; j += 2) {
            float2 f = __half22float2(*(const __half2*)(row + j));
            s += f.x + f.y;
        }
        pts[tt2][dk] = s;
    }
    __syncthreads();
    if (tid < 64) {
        float run = 0.f;
        for (int tt = 15; tt >= 0; tt--) {
            g_Suf[((size_t)bh * 16 + tt) * 64 + tid] = run;
            run += pts[tt][tid];
        }
    }
}

// ---------------- head-axis softmax -> fp16 P (lower tiles only) ----------------
__global__ void __launch_bounds__(256) softmax_heads(const int* __restrict__ mask) {
    size_t e = ((size_t)blockIdx.x * 256 + threadIdx.x) * 4;
    int b = (int)(e >> 22);
    size_t r = e & (SSZ - 1);
    int q = (int)(r >> 11), k0 = (int)(r & 2047);
    if ((k0 >> 7) > (q >> 7)) return;   // upper tile: P never read
    int4 mk = *(const int4*)(mask + (size_t)q * 2048 + k0);
    int mks[4] = {mk.x, mk.y, mk.z, mk.w};
    float sv[16][4];
    if (mk.x | mk.y | mk.z | mk.w) {
#pragma unroll
        for (int h = 0; h < 16; h++)
            *(float4*)sv[h] = *(const float4*)(g_Scr + (size_t)(b * 16 + h) * SSZ + r);
    }
    ushort hs[16][4];
#pragma unroll
    for (int j = 0; j < 4; j++) {
        if (!mks[j]) {
#pragma unroll
            for (int h = 0; h < 16; h++) hs[h][j] = 0x2C00;  // 1/16 exact
        } else {
            float mx = -3.4e38f;
#pragma unroll
            for (int h = 0; h < 16; h++) mx = fmaxf(mx, sv[h][j]);
            float sum = 0.f, ev[16];
#pragma unroll
            for (int h = 0; h < 16; h++) { ev[h] = __expf(sv[h][j] - mx); sum += ev[h]; }
            float inv = 1.f / sum;
#pragma unroll
            for (int h = 0; h < 16; h++) hs[h][j] = __half_as_ushort(__float2half_rn(ev[h] * inv));
        }
    }
#pragma unroll
    for (int h = 0; h < 16; h++) {
        uint2 pk;
        pk.x = (uint32_t)hs[h][0] | ((uint32_t)hs[h][1] << 16);
        pk.y = (uint32_t)hs[h][2] | ((uint32_t)hs[h][3] << 16);
        *(uint2*)(g_P16 + (size_t)(b * 16 + h) * SSZ + r) = pk;
    }
}

// ---------------- launch ----------------
extern "C" void kernel_launch(void* const* d_in, const int* in_sizes, int n_in,
                              void* d_out, int out_size) {
    const float* q    = (const float*)d_in[0];
    const float* k    = (const float*)d_in[1];
    const float* v    = (const float*)d_in[2];
    const int*   mask = (const int*)  d_in[3];
    const float* wq_b = (const float*)d_in[5];
    const float* wk_b = (const float*)d_in[7];
    const float* wv_b = (const float*)d_in[9];
    const float* wo_b = (const float*)d_in[11];
    float* out = (float*)d_out;

    cvt_split<<<4096, 256>>>(q, 0);
    cvt_split<<<4096, 256>>>(k, 1);
    cvt_split<<<4096, 256>>>(v, 2);
    cvt_split<<<1024, 256>>>((const float*)d_in[4], 3);
    cvt_split<<<1024, 256>>>((const float*)d_in[6], 4);
    cvt_split<<<1024, 256>>>((const float*)d_in[8], 5);
    cvt_split<<<1024, 256>>>((const float*)d_in[10], 6);

    gemm_mma<0><<<dim3(8, 32, 1), 256>>>(wq_b, nullptr);
    gemm_mma<1><<<dim3(8, 32, 1), 256>>>(wk_b, nullptr);
    gemm_mma<2><<<dim3(8, 32, 1), 256>>>(wv_b, nullptr);

    suffix_k<<<32, 256>>>();

    gemm_mma<4><<<dim3(16, 16, 32), 256>>>(nullptr, nullptr);

    softmax_heads<<<8192, 256>>>(mask);

    gemm_mma<5><<<dim3(1, 16, 32), 256>>>(nullptr, nullptr);

    gemm_mma<3><<<dim3(8, 32, 1), 256>>>(wo_b, out);
}

// round 12
// speedup vs baseline: 3.7550x; 2.0002x over previous
#include <cuda_runtime.h>
#include <cuda_fp16.h>
#include <cstdint>

#define SSZ 4194304ull   // S*S
#define TPITCH 144       // bytes per smem tile row (64 halves + 8 pad)
#define TILE   18432     // 128 rows * 144B

// ---------------- device scratch ----------------
__device__ __half g_Xh[12582912], g_Xl[12582912];   // q,k,v split [3][4096,1024]
__device__ __half g_Wh[4194304],  g_Wl[4194304];    // wq,wk,wv,wo split [4][1024,1024]
__device__ __half g_Qh[4194304],  g_Ql[4194304];    // [bh,s,64]
__device__ __half g_Kh[4194304],  g_Kl[4194304];    // [bh,s,64]
__device__ __half g_Vt[4194304];                    // V transposed [bh,64,s]
__device__ float  g_Suf[32768];                     // [bh][16][64] suffix tile sums
__device__ float  g_Scr[134217728];                 // scores fp32 (lower tiles)
__device__ __half g_P16[134217728];                 // probs fp16 (lower tiles)
__device__ __half g_Oh[4194304],  g_Ol[4194304];    // context split [4096,1024]

__device__ __forceinline__ void mma16816(float* c, const uint32_t* a, uint32_t b0, uint32_t b1) {
    asm volatile(
        "mma.sync.aligned.m16n8k16.row.col.f32.f16.f16.f32 "
        "{%0,%1,%2,%3}, {%4,%5,%6,%7}, {%8,%9}, {%0,%1,%2,%3};"
        : "+f"(c[0]), "+f"(c[1]), "+f"(c[2]), "+f"(c[3])
        : "r"(a[0]), "r"(a[1]), "r"(a[2]), "r"(a[3]), "r"(b0), "r"(b1));
}
__device__ __forceinline__ void ldsm4(uint32_t* r, uint32_t a) {
    asm volatile("ldmatrix.sync.aligned.m8n8.x4.shared.b16 {%0,%1,%2,%3}, [%4];"
                 : "=r"(r[0]), "=r"(r[1]), "=r"(r[2]), "=r"(r[3]) : "r"(a));
}
__device__ __forceinline__ void cpa16(uint32_t s, const void* g) {
    asm volatile("cp.async.ca.shared.global [%0], [%1], 16;" :: "r"(s), "l"(g));
}
#define CP_COMMIT() asm volatile("cp.async.commit_group;" ::: "memory")
#define CP_WAIT(n)  asm volatile("cp.async.wait_group %0;" :: "n"(n) : "memory")

// ---------------- fp32 -> hi/lo fp16 split ----------------
__global__ void __launch_bounds__(256) cvt_split(const float* __restrict__ src, int slot) {
    int i = blockIdx.x * 256 + threadIdx.x;
    __half* H = (slot < 3) ? g_Xh + (size_t)slot * 4194304ull : g_Wh + (size_t)(slot - 3) * 1048576ull;
    __half* L = (slot < 3) ? g_Xl + (size_t)slot * 4194304ull : g_Wl + (size_t)(slot - 3) * 1048576ull;
    float4 x = reinterpret_cast<const float4*>(src)[i];
    __half h0 = __float2half_rn(x.x), h1 = __float2half_rn(x.y);
    __half h2 = __float2half_rn(x.z), h3 = __float2half_rn(x.w);
    uint2 oh, ol;
    oh.x = (uint32_t)__half_as_ushort(h0) | ((uint32_t)__half_as_ushort(h1) << 16);
    oh.y = (uint32_t)__half_as_ushort(h2) | ((uint32_t)__half_as_ushort(h3) << 16);
    ol.x = (uint32_t)__half_as_ushort(__float2half_rn(x.x - __half2float(h0))) |
           ((uint32_t)__half_as_ushort(__float2half_rn(x.y - __half2float(h1))) << 16);
    ol.y = (uint32_t)__half_as_ushort(__float2half_rn(x.z - __half2float(h2))) |
           ((uint32_t)__half_as_ushort(__float2half_rn(x.w - __half2float(h3))) << 16);
    reinterpret_cast<uint2*>(H)[i] = oh;
    reinterpret_cast<uint2*>(L)[i] = ol;
}

// ---------------- pipelined HMMA GEMM (C = A . B^T) ----------------
// MODE 0/1: X.W^T+b -> Q/K head-split hi/lo.  MODE 2: -> Vt transposed fp16.
// MODE 3: O.Wo^T+b -> fp32 out.  MODE 4: Q.K^T/8 lower tiles -> g_Scr.
// MODE 5: P.V (k-tiles<=bm) + (1/16)*suffix -> g_Oh/g_Ol.
template <int MODE>
__global__ void __launch_bounds__(256) gemm_mma(const float* __restrict__ bias,
                                                float* __restrict__ out32) {
    constexpr int NT  = (MODE == 5) ? 64 : 128;
    constexpr int WNN = NT / 32;
    constexpr int RW  = 16 * WNN;          // 64 (modes<=4) / 32 (mode5)
    constexpr int MI  = RW / 16;
    constexpr int CHB = (MODE == 5) ? (TILE + 9216) : 4 * TILE;

    const int bn = blockIdx.x, bm = blockIdx.y, bh = blockIdx.z;
    if (MODE == 4 && bn > bm) return;

    extern __shared__ __align__(16) char dsm[];
    const uint32_t smb = (uint32_t)__cvta_generic_to_shared(dsm);

    const int tid = threadIdx.x, lane = tid & 31, wid = tid >> 5;
    const int g = lane >> 2, t = lane & 3;
    const int wn = wid % WNN, wm = wid / WNN;

    const __half *Ahi = nullptr, *Alo = nullptr, *Bhi = nullptr, *Blo = nullptr;
    int lda = 1024, ldb = 1024, NCH = 16;
    const int arow0 = bm * 128, brow0 = bn * NT;
    if (MODE == 0) { Ahi = g_Xh;              Alo = g_Xl;              Bhi = g_Wh;              Blo = g_Wl; }
    if (MODE == 1) { Ahi = g_Xh + 4194304ull; Alo = g_Xl + 4194304ull; Bhi = g_Wh + 1048576ull; Blo = g_Wl + 1048576ull; }
    if (MODE == 2) { Ahi = g_Xh + 8388608ull; Alo = g_Xl + 8388608ull; Bhi = g_Wh + 2097152ull; Blo = g_Wl + 2097152ull; }
    if (MODE == 3) { Ahi = g_Oh;              Alo = g_Ol;              Bhi = g_Wh + 3145728ull; Blo = g_Wl + 3145728ull; }
    if (MODE == 4) { size_t o = (size_t)bh * 131072ull;
                     Ahi = g_Qh + o; Alo = g_Ql + o; Bhi = g_Kh + o; Blo = g_Kl + o;
                     lda = ldb = 64; NCH = 1; }
    if (MODE == 5) { Ahi = g_P16 + (size_t)bh * SSZ; Bhi = g_Vt + (size_t)bh * 131072ull;
                     lda = 2048; ldb = 2048; NCH = 2 * (bm + 1); }

    float acc[MI][4][4];
#pragma unroll
    for (int mi = 0; mi < MI; mi++)
#pragma unroll
        for (int ni = 0; ni < 4; ni++)
#pragma unroll
            for (int j = 0; j < 4; j++) acc[mi][ni][j] = 0.f;

    auto stage = [&](int c, int bsel) {
        uint32_t sb = smb + bsel * CHB;
        int ko = c * 64;
        if (MODE <= 4) {
            for (int i = tid; i < 1024; i += 256) {
                int r = i >> 3, cb = (i & 7) << 4;
                cpa16(sb + r * TPITCH + cb,            (const char*)(Ahi + (size_t)(arow0 + r) * lda + ko) + cb);
                cpa16(sb + TILE + r * TPITCH + cb,     (const char*)(Alo + (size_t)(arow0 + r) * lda + ko) + cb);
                cpa16(sb + 2 * TILE + r * TPITCH + cb, (const char*)(Bhi + (size_t)(brow0 + r) * ldb + ko) + cb);
                cpa16(sb + 3 * TILE + r * TPITCH + cb, (const char*)(Blo + (size_t)(brow0 + r) * ldb + ko) + cb);
            }
        } else {
            for (int i = tid; i < 1024; i += 256) {
                int r = i >> 3, cb = (i & 7) << 4;
                cpa16(sb + r * TPITCH + cb, (const char*)(Ahi + (size_t)(arow0 + r) * 2048 + ko) + cb);
            }
            for (int i = tid; i < 512; i += 256) {
                int r = i >> 3, cb = (i & 7) << 4;
                cpa16(sb + TILE + r * TPITCH + cb, (const char*)(Bhi + (size_t)r * 2048 + ko) + cb);
            }
        }
        CP_COMMIT();
    };

    const int arl  = lane & 15;
    const int asel = (lane >> 4) << 4;                     // bytes
    const int brl  = ((lane >> 4) << 3) + (lane & 7);
    const int bsl  = ((lane >> 3) & 1) << 4;               // bytes

    auto compute = [&](int bsel) {
        uint32_t tA  = smb + bsel * CHB;
        uint32_t tAl = tA + TILE;
        uint32_t tBh = (MODE == 5) ? tA + TILE : tA + 2 * TILE;
        uint32_t tBl = tA + 3 * TILE;
#pragma unroll
        for (int kk = 0; kk < 4; kk++) {
            int kb = kk * 32;
            uint32_t ah[MI][4];
#pragma unroll
            for (int mi = 0; mi < MI; mi++)
                ldsm4(ah[mi], tA + (wm * RW + mi * 16 + arl) * TPITCH + kb + asel);
            uint32_t bhf[8];
#pragma unroll
            for (int p = 0; p < 2; p++)
                ldsm4(&bhf[p * 4], tBh + (wn * 32 + p * 16 + brl) * TPITCH + kb + bsl);
            if (MODE <= 4) {
                uint32_t alf[MI][4], blf[8];
#pragma unroll
                for (int mi = 0; mi < MI; mi++)
                    ldsm4(alf[mi], tAl + (wm * RW + mi * 16 + arl) * TPITCH + kb + asel);
#pragma unroll
                for (int p = 0; p < 2; p++)
                    ldsm4(&blf[p * 4], tBl + (wn * 32 + p * 16 + brl) * TPITCH + kb + bsl);
#pragma unroll
                for (int ni = 0; ni < 4; ni++)
#pragma unroll
                    for (int mi = 0; mi < MI; mi++) {
                        mma16816(acc[mi][ni], ah[mi],  bhf[2 * ni], bhf[2 * ni + 1]);
                        mma16816(acc[mi][ni], ah[mi],  blf[2 * ni], blf[2 * ni + 1]);
                        mma16816(acc[mi][ni], alf[mi], bhf[2 * ni], bhf[2 * ni + 1]);
                    }
            } else {
#pragma unroll
                for (int ni = 0; ni < 4; ni++)
#pragma unroll
                    for (int mi = 0; mi < MI; mi++)
                        mma16816(acc[mi][ni], ah[mi], bhf[2 * ni], bhf[2 * ni + 1]);
            }
        }
    };

    stage(0, 0);
    for (int c = 0; c < NCH; c++) {
        if (c + 1 < NCH) { stage(c + 1, (c + 1) & 1); CP_WAIT(1); }
        else             { CP_WAIT(0); }
        __syncthreads();
        compute(c & 1);
        __syncthreads();
    }

    // ---- epilogues ----
    if (MODE <= 3) {
#pragma unroll
        for (int ni = 0; ni < 4; ni++) {
            int col = bn * 128 + wn * 32 + ni * 8 + 2 * t;
            float2 bv = *(const float2*)&bias[col];
#pragma unroll
            for (int mi = 0; mi < MI; mi++) {
                acc[mi][ni][0] += bv.x; acc[mi][ni][1] += bv.y;
                acc[mi][ni][2] += bv.x; acc[mi][ni][3] += bv.y;
            }
        }
    }
    if (MODE == 5) {
#pragma unroll
        for (int ni = 0; ni < 4; ni++) {
            int dk = wn * 32 + ni * 8 + 2 * t;
            float2 sv = *(const float2*)&g_Suf[((size_t)bh * 16 + bm) * 64 + dk];
#pragma unroll
            for (int mi = 0; mi < MI; mi++) {
                acc[mi][ni][0] += 0.0625f * sv.x; acc[mi][ni][1] += 0.0625f * sv.y;
                acc[mi][ni][2] += 0.0625f * sv.x; acc[mi][ni][3] += 0.0625f * sv.y;
            }
        }
    }

    if (MODE == 3) {
#pragma unroll
        for (int mi = 0; mi < MI; mi++)
#pragma unroll
            for (int ni = 0; ni < 4; ni++) {
                int r0 = bm * 128 + wm * RW + mi * 16 + g;
                int cl = bn * 128 + wn * 32 + ni * 8 + 2 * t;
                *(float2*)&out32[(size_t)r0 * 1024 + cl]       = make_float2(acc[mi][ni][0], acc[mi][ni][1]);
                *(float2*)&out32[(size_t)(r0 + 8) * 1024 + cl] = make_float2(acc[mi][ni][2], acc[mi][ni][3]);
            }
        return;
    }
    if (MODE == 4) {
        float* Sd = g_Scr + (size_t)bh * SSZ;
#pragma unroll
        for (int mi = 0; mi < MI; mi++)
#pragma unroll
            for (int ni = 0; ni < 4; ni++) {
                int q0 = bm * 128 + wm * RW + mi * 16 + g;
                int cl = bn * 128 + wn * 32 + ni * 8 + 2 * t;
                *(float2*)&Sd[(size_t)q0 * 2048 + cl]       = make_float2(acc[mi][ni][0] * 0.125f, acc[mi][ni][1] * 0.125f);
                *(float2*)&Sd[(size_t)(q0 + 8) * 2048 + cl] = make_float2(acc[mi][ni][2] * 0.125f, acc[mi][ni][3] * 0.125f);
            }
        return;
    }

    // bounce-buffer epilogues (smem reuse), pitch 136 halves
    __half* bb = (__half*)dsm;
    const int NPASS = (MODE == 2) ? 1 : 2;
    for (int pass = 0; pass < NPASS; pass++) {
        __syncthreads();
#pragma unroll
        for (int mi = 0; mi < MI; mi++)
#pragma unroll
            for (int ni = 0; ni < 4; ni++) {
                int r0 = wm * RW + mi * 16 + g;
                int cl = wn * 32 + ni * 8 + 2 * t;
                float v0 = acc[mi][ni][0], v1 = acc[mi][ni][1];
                float v2 = acc[mi][ni][2], v3 = acc[mi][ni][3];
                if (pass == 1) {
                    v0 -= __half2float(__float2half_rn(v0));
                    v1 -= __half2float(__float2half_rn(v1));
                    v2 -= __half2float(__float2half_rn(v2));
                    v3 -= __half2float(__float2half_rn(v3));
                }
                *(__half2*)&bb[r0 * 136 + cl]       = __floats2half2_rn(v0, v1);
                *(__half2*)&bb[(r0 + 8) * 136 + cl] = __floats2half2_rn(v2, v3);
            }
        __syncthreads();
        if (MODE <= 1) {
            __half* D = pass ? (MODE ? g_Kl : g_Ql) : (MODE ? g_Kh : g_Qh);
            for (int i = tid; i < 2048; i += 256) {
                int r = i >> 4, c8 = (i & 15) << 3;
                int m = bm * 128 + r, n = bn * 128 + c8;
                size_t dst = ((size_t)((m >> 11) * 16 + (n >> 6)) * 2048 + (m & 2047)) * 64 + (n & 63);
                *(uint4*)&D[dst] = *(const uint4*)&bb[r * 136 + c8];
            }
        } else if (MODE == 5) {
            __half* D = pass ? g_Ol : g_Oh;
            for (int i = tid; i < 1024; i += 256) {
                int r = i >> 3, c8 = (i & 7) << 3;
                size_t dst = ((size_t)(bh >> 4) * 2048 + bm * 128 + r) * 1024 + (bh & 15) * 64 + c8;
                *(uint4*)&D[dst] = *(const uint4*)&bb[r * 136 + c8];
            }
        } else {  // MODE 2: transposed store -> g_Vt
            for (int i = tid; i < 2048; i += 256) {
                int nn = i >> 4, s8 = (i & 15) << 3;
                int n = bn * 128 + nn;
                int b2 = (bm * 128) >> 11, h2 = n >> 6, dk = n & 63;
                union { uint4 q; ushort u[8]; } pk;
#pragma unroll
                for (int j = 0; j < 8; j++)
                    pk.u[j] = __half_as_ushort(bb[(s8 + j) * 136 + nn]);
                size_t dst = ((size_t)(b2 * 16 + h2) * 64 + dk) * 2048 + ((bm * 128) & 2047) + s8;
                *(uint4*)&g_Vt[dst] = pk.q;
            }
        }
    }
}

// ---------------- suffix tile sums of V ----------------
__global__ void __launch_bounds__(256) suffix_k() {
    __shared__ float pts[16][64];
    int bh = blockIdx.x, tid = threadIdx.x, dk = tid & 63, p = tid >> 6;
    for (int tt = 0; tt < 4; tt++) {
        int tt2 = p * 4 + tt;
        const __half* row = g_Vt + ((size_t)bh * 64 + dk) * 2048 + tt2 * 128;
        float s = 0.f;
        for (int j = 0; j < 128; j += 2) {
            float2 f = __half22float2(*(const __half2*)(row + j));
            s += f.x + f.y;
        }
        pts[tt2][dk] = s;
    }
    __syncthreads();
    if (tid < 64) {
        float run = 0.f;
        for (int tt = 15; tt >= 0; tt--) {
            g_Suf[((size_t)bh * 16 + tt) * 64 + tid] = run;
            run += pts[tt][tid];
        }
    }
}

// ---------------- head-axis softmax -> fp16 P (lower tiles only) ----------------
__global__ void __launch_bounds__(256) softmax_heads(const int* __restrict__ mask) {
    size_t e = ((size_t)blockIdx.x * 256 + threadIdx.x) * 4;
    int b = (int)(e >> 22);
    size_t r = e & (SSZ - 1);
    int q = (int)(r >> 11), k0 = (int)(r & 2047);
    if ((k0 >> 7) > (q >> 7)) return;   // upper tile: P never read
    int4 mk = *(const int4*)(mask + (size_t)q * 2048 + k0);
    int mks[4] = {mk.x, mk.y, mk.z, mk.w};
    float sv[16][4];
    if (mk.x | mk.y | mk.z | mk.w) {
#pragma unroll
        for (int h = 0; h < 16; h++)
            *(float4*)sv[h] = *(const float4*)(g_Scr + (size_t)(b * 16 + h) * SSZ + r);
    }
    ushort hs[16][4];
#pragma unroll
    for (int j = 0; j < 4; j++) {
        if (!mks[j]) {
#pragma unroll
            for (int h = 0; h < 16; h++) hs[h][j] = 0x2C00;  // 1/16 exact
        } else {
            float mx = -3.4e38f;
#pragma unroll
            for (int h = 0; h < 16; h++) mx = fmaxf(mx, sv[h][j]);
            float sum = 0.f, ev[16];
#pragma unroll
            for (int h = 0; h < 16; h++) { ev[h] = __expf(sv[h][j] - mx); sum += ev[h]; }
            float inv = 1.f / sum;
#pragma unroll
            for (int h = 0; h < 16; h++) hs[h][j] = __half_as_ushort(__float2half_rn(ev[h] * inv));
        }
    }
#pragma unroll
    for (int h = 0; h < 16; h++) {
        uint2 pk;
        pk.x = (uint32_t)hs[h][0] | ((uint32_t)hs[h][1] << 16);
        pk.y = (uint32_t)hs[h][2] | ((uint32_t)hs[h][3] << 16);
        *(uint2*)(g_P16 + (size_t)(b * 16 + h) * SSZ + r) = pk;
    }
}

// ---------------- launch ----------------
extern "C" void kernel_launch(void* const* d_in, const int* in_sizes, int n_in,
                              void* d_out, int out_size) {
    const float* q    = (const float*)d_in[0];
    const float* k    = (const float*)d_in[1];
    const float* v    = (const float*)d_in[2];
    const int*   mask = (const int*)  d_in[3];
    const float* wq_b = (const float*)d_in[5];
    const float* wk_b = (const float*)d_in[7];
    const float* wv_b = (const float*)d_in[9];
    const float* wo_b = (const float*)d_in[11];
    float* out = (float*)d_out;

    const int SM03 = 2 * 4 * TILE;       // 147456
    const int SM4  = 4 * TILE;           // 73728
    const int SM5  = 2 * (TILE + 9216);  // 55296
    static bool attr_done = false;
    if (!attr_done) {
        cudaFuncSetAttribute(gemm_mma<0>, cudaFuncAttributeMaxDynamicSharedMemorySize, SM03);
        cudaFuncSetAttribute(gemm_mma<1>, cudaFuncAttributeMaxDynamicSharedMemorySize, SM03);
        cudaFuncSetAttribute(gemm_mma<2>, cudaFuncAttributeMaxDynamicSharedMemorySize, SM03);
        cudaFuncSetAttribute(gemm_mma<3>, cudaFuncAttributeMaxDynamicSharedMemorySize, SM03);
        cudaFuncSetAttribute(gemm_mma<4>, cudaFuncAttributeMaxDynamicSharedMemorySize, SM4);
        cudaFuncSetAttribute(gemm_mma<5>, cudaFuncAttributeMaxDynamicSharedMemorySize, SM5);
        attr_done = true;
    }

    cvt_split<<<4096, 256>>>(q, 0);
    cvt_split<<<4096, 256>>>(k, 1);
    cvt_split<<<4096, 256>>>(v, 2);
    cvt_split<<<1024, 256>>>((const float*)d_in[4], 3);
    cvt_split<<<1024, 256>>>((const float*)d_in[6], 4);
    cvt_split<<<1024, 256>>>((const float*)d_in[8], 5);
    cvt_split<<<1024, 256>>>((const float*)d_in[10], 6);

    gemm_mma<0><<<dim3(8, 32, 1), 256, SM03>>>(wq_b, nullptr);
    gemm_mma<1><<<dim3(8, 32, 1), 256, SM03>>>(wk_b, nullptr);
    gemm_mma<2><<<dim3(8, 32, 1), 256, SM03>>>(wv_b, nullptr);

    suffix_k<<<32, 256>>>();

    gemm_mma<4><<<dim3(16, 16, 32), 256, SM4>>>(nullptr, nullptr);

    softmax_heads<<<8192, 256>>>(mask);

    gemm_mma<5><<<dim3(1, 16, 32), 256, SM5>>>(nullptr, nullptr);

    gemm_mma<3><<<dim3(8, 32, 1), 256, SM03>>>(wo_b, out);
}

// round 17
// speedup vs baseline: 5.6357x; 1.5009x over previous
#include <cuda_runtime.h>
#include <cuda_fp16.h>
#include <cstdint>

#define SSZ 4194304ull   // S*S
#define TPITCH 144       // bytes per smem tile row (64 halves + 8 pad)
#define TILE   18432     // 128 rows * 144B

// ---------------- device scratch ----------------
__device__ __half g_X16[12582912];   // q,k,v fp16 [3][4096,1024]
__device__ __half g_W16[4194304];    // wq,wk,wv,wo fp16 [4][1024,1024]
__device__ __half g_Q16[4194304];    // [bh,s,64]
__device__ __half g_K16[4194304];    // [bh,s,64]
__device__ __half g_Vt[4194304];     // V transposed [bh,64,s]
__device__ float  g_Suf[32768];      // [bh][16][64] suffix tile sums
__device__ float  g_Scr[134217728];  // scores fp32 (lower tiles)
__device__ __half g_P16[134217728];  // probs fp16 (lower tiles)
__device__ __half g_O16[4194304];    // context fp16 [4096,1024]

__device__ __forceinline__ void mma16816(float* c, const uint32_t* a, uint32_t b0, uint32_t b1) {
    asm volatile(
        "mma.sync.aligned.m16n8k16.row.col.f32.f16.f16.f32 "
        "{%0,%1,%2,%3}, {%4,%5,%6,%7}, {%8,%9}, {%0,%1,%2,%3};"
        : "+f"(c[0]), "+f"(c[1]), "+f"(c[2]), "+f"(c[3])
        : "r"(a[0]), "r"(a[1]), "r"(a[2]), "r"(a[3]), "r"(b0), "r"(b1));
}
__device__ __forceinline__ void ldsm4(uint32_t* r, uint32_t a) {
    asm volatile("ldmatrix.sync.aligned.m8n8.x4.shared.b16 {%0,%1,%2,%3}, [%4];"
                 : "=r"(r[0]), "=r"(r[1]), "=r"(r[2]), "=r"(r[3]) : "r"(a));
}
__device__ __forceinline__ void cpa16(uint32_t s, const void* g) {
    asm volatile("cp.async.ca.shared.global [%0], [%1], 16;" :: "r"(s), "l"(g));
}
#define CP_COMMIT() asm volatile("cp.async.commit_group;" ::: "memory")
#define CP_WAIT(n)  asm volatile("cp.async.wait_group %0;" :: "n"(n) : "memory")

// ---------------- fp32 -> fp16 ----------------
__global__ void __launch_bounds__(256) cvt16(const float* __restrict__ src, int slot) {
    int i = blockIdx.x * 256 + threadIdx.x;
    __half* H = (slot < 3) ? g_X16 + (size_t)slot * 4194304ull : g_W16 + (size_t)(slot - 3) * 1048576ull;
    float4 x = reinterpret_cast<const float4*>(src)[i];
    uint2 oh;
    oh.x = (uint32_t)__half_as_ushort(__float2half_rn(x.x)) |
           ((uint32_t)__half_as_ushort(__float2half_rn(x.y)) << 16);
    oh.y = (uint32_t)__half_as_ushort(__float2half_rn(x.z)) |
           ((uint32_t)__half_as_ushort(__float2half_rn(x.w)) << 16);
    reinterpret_cast<uint2*>(H)[i] = oh;
}

// ---------------- pipelined HMMA GEMM (C = A . B^T) ----------------
// MODE 0/1: X.W^T+b -> Q/K head-split fp16.  MODE 2: -> Vt transposed fp16.
// MODE 3: O.Wo^T+b -> fp32 out.  MODE 4: Q.K^T/8 lower tiles -> g_Scr.
// MODE 5: P.V (k-tiles<=bm) + (1/16)*suffix -> g_O16.
template <int MODE>
__global__ void __launch_bounds__(256) gemm_mma(const float* __restrict__ bias,
                                                float* __restrict__ out32) {
    constexpr int NT  = (MODE == 5) ? 64 : 128;
    constexpr int WNN = NT / 32;
    constexpr int RW  = 16 * WNN;          // 64 (modes<=4) / 32 (mode5)
    constexpr int MI  = RW / 16;
    constexpr int CHB = TILE + NT * TPITCH;

    const int bn = blockIdx.x, bm = blockIdx.y, bh = blockIdx.z;
    if (MODE == 4 && bn > bm) return;

    extern __shared__ __align__(16) char dsm[];
    const uint32_t smb = (uint32_t)__cvta_generic_to_shared(dsm);

    const int tid = threadIdx.x, lane = tid & 31, wid = tid >> 5;
    const int g = lane >> 2, t = lane & 3;
    const int wn = wid % WNN, wm = wid / WNN;

    const __half *A = nullptr, *Bt = nullptr;
    int lda = 1024, ldb = 1024, NCH = 16;
    const int arow0 = bm * 128, brow0 = (MODE == 5) ? 0 : bn * NT;
    if (MODE == 0) { A = g_X16;              Bt = g_W16; }
    if (MODE == 1) { A = g_X16 + 4194304ull; Bt = g_W16 + 1048576ull; }
    if (MODE == 2) { A = g_X16 + 8388608ull; Bt = g_W16 + 2097152ull; }
    if (MODE == 3) { A = g_O16;              Bt = g_W16 + 3145728ull; }
    if (MODE == 4) { size_t o = (size_t)bh * 131072ull;
                     A = g_Q16 + o; Bt = g_K16 + o; lda = ldb = 64; NCH = 1; }
    if (MODE == 5) { A = g_P16 + (size_t)bh * SSZ; Bt = g_Vt + (size_t)bh * 131072ull;
                     lda = 2048; ldb = 2048; NCH = 2 * (bm + 1); }

    float acc[MI][4][4];
#pragma unroll
    for (int mi = 0; mi < MI; mi++)
#pragma unroll
        for (int ni = 0; ni < 4; ni++)
#pragma unroll
            for (int j = 0; j < 4; j++) acc[mi][ni][j] = 0.f;

    auto stage = [&](int c, int bsel) {
        uint32_t sb = smb + bsel * CHB;
        int ko = c * 64;
        for (int i = tid; i < 1024; i += 256) {
            int r = i >> 3, cb = (i & 7) << 4;
            cpa16(sb + r * TPITCH + cb, (const char*)(A + (size_t)(arow0 + r) * lda + ko) + cb);
            if (NT == 128)
                cpa16(sb + TILE + r * TPITCH + cb, (const char*)(Bt + (size_t)(brow0 + r) * ldb + ko) + cb);
        }
        if (NT == 64) {
            for (int i = tid; i < 512; i += 256) {
                int r = i >> 3, cb = (i & 7) << 4;
                cpa16(sb + TILE + r * TPITCH + cb, (const char*)(Bt + (size_t)(brow0 + r) * ldb + ko) + cb);
            }
        }
        CP_COMMIT();
    };

    const int arl  = lane & 15;
    const int asel = (lane >> 4) << 4;                     // bytes
    const int brl  = ((lane >> 4) << 3) + (lane & 7);
    const int bsl  = ((lane >> 3) & 1) << 4;               // bytes

    auto compute = [&](int bsel) {
        uint32_t tA = smb + bsel * CHB;
        uint32_t tB = tA + TILE;
#pragma unroll
        for (int kk = 0; kk < 4; kk++) {
            int kb = kk * 32;
            uint32_t ah[MI][4];
#pragma unroll
            for (int mi = 0; mi < MI; mi++)
                ldsm4(ah[mi], tA + (wm * RW + mi * 16 + arl) * TPITCH + kb + asel);
            uint32_t bhf[8];
#pragma unroll
            for (int p = 0; p < 2; p++)
                ldsm4(&bhf[p * 4], tB + (wn * 32 + p * 16 + brl) * TPITCH + kb + bsl);
#pragma unroll
            for (int ni = 0; ni < 4; ni++)
#pragma unroll
                for (int mi = 0; mi < MI; mi++)
                    mma16816(acc[mi][ni], ah[mi], bhf[2 * ni], bhf[2 * ni + 1]);
        }
    };

    stage(0, 0);
    for (int c = 0; c < NCH; c++) {
        if (c + 1 < NCH) { stage(c + 1, (c + 1) & 1); CP_WAIT(1); }
        else             { CP_WAIT(0); }
        __syncthreads();
        compute(c & 1);
        __syncthreads();
    }

    // ---- epilogues ----
    if (MODE <= 3) {
#pragma unroll
        for (int ni = 0; ni < 4; ni++) {
            int col = bn * 128 + wn * 32 + ni * 8 + 2 * t;
            float2 bv = *(const float2*)&bias[col];
#pragma unroll
            for (int mi = 0; mi < MI; mi++) {
                acc[mi][ni][0] += bv.x; acc[mi][ni][1] += bv.y;
                acc[mi][ni][2] += bv.x; acc[mi][ni][3] += bv.y;
            }
        }
    }
    if (MODE == 5) {
#pragma unroll
        for (int ni = 0; ni < 4; ni++) {
            int dk = wn * 32 + ni * 8 + 2 * t;
            float2 sv = *(const float2*)&g_Suf[((size_t)bh * 16 + bm) * 64 + dk];
#pragma unroll
            for (int mi = 0; mi < MI; mi++) {
                acc[mi][ni][0] += 0.0625f * sv.x; acc[mi][ni][1] += 0.0625f * sv.y;
                acc[mi][ni][2] += 0.0625f * sv.x; acc[mi][ni][3] += 0.0625f * sv.y;
            }
        }
    }

    if (MODE == 3) {
#pragma unroll
        for (int mi = 0; mi < MI; mi++)
#pragma unroll
            for (int ni = 0; ni < 4; ni++) {
                int r0 = bm * 128 + wm * RW + mi * 16 + g;
                int cl = bn * 128 + wn * 32 + ni * 8 + 2 * t;
                *(float2*)&out32[(size_t)r0 * 1024 + cl]       = make_float2(acc[mi][ni][0], acc[mi][ni][1]);
                *(float2*)&out32[(size_t)(r0 + 8) * 1024 + cl] = make_float2(acc[mi][ni][2], acc[mi][ni][3]);
            }
        return;
    }
    if (MODE == 4) {
        float* Sd = g_Scr + (size_t)bh * SSZ;
#pragma unroll
        for (int mi = 0; mi < MI; mi++)
#pragma unroll
            for (int ni = 0; ni < 4; ni++) {
                int q0 = bm * 128 + wm * RW + mi * 16 + g;
                int cl = bn * 128 + wn * 32 + ni * 8 + 2 * t;
                *(float2*)&Sd[(size_t)q0 * 2048 + cl]       = make_float2(acc[mi][ni][0] * 0.125f, acc[mi][ni][1] * 0.125f);
                *(float2*)&Sd[(size_t)(q0 + 8) * 2048 + cl] = make_float2(acc[mi][ni][2] * 0.125f, acc[mi][ni][3] * 0.125f);
            }
        return;
    }

    // fp16 bounce-buffer epilogues (smem reuse), pitch 136 halves
    __half* bb = (__half*)dsm;
    __syncthreads();
#pragma unroll
    for (int mi = 0; mi < MI; mi++)
#pragma unroll
        for (int ni = 0; ni < 4; ni++) {
            int r0 = wm * RW + mi * 16 + g;
            int cl = wn * 32 + ni * 8 + 2 * t;
            *(__half2*)&bb[r0 * 136 + cl]       = __floats2half2_rn(acc[mi][ni][0], acc[mi][ni][1]);
            *(__half2*)&bb[(r0 + 8) * 136 + cl] = __floats2half2_rn(acc[mi][ni][2], acc[mi][ni][3]);
        }
    __syncthreads();
    if (MODE <= 1) {
        __half* D = MODE ? g_K16 : g_Q16;
        for (int i = tid; i < 2048; i += 256) {
            int r = i >> 4, c8 = (i & 15) << 3;
            int m = bm * 128 + r, n = bn * 128 + c8;
            size_t dst = ((size_t)((m >> 11) * 16 + (n >> 6)) * 2048 + (m & 2047)) * 64 + (n & 63);
            *(uint4*)&D[dst] = *(const uint4*)&bb[r * 136 + c8];
        }
    } else if (MODE == 5) {
        for (int i = tid; i < 1024; i += 256) {
            int r = i >> 3, c8 = (i & 7) << 3;
            size_t dst = ((size_t)(bh >> 4) * 2048 + bm * 128 + r) * 1024 + (bh & 15) * 64 + c8;
            *(uint4*)&g_O16[dst] = *(const uint4*)&bb[r * 136 + c8];
        }
    } else {  // MODE 2: transposed store -> g_Vt
        for (int i = tid; i < 2048; i += 256) {
            int nn = i >> 4, s8 = (i & 15) << 3;
            int n = bn * 128 + nn;
            int b2 = (bm * 128) >> 11, h2 = n >> 6, dk = n & 63;
            union { uint4 q; ushort u[8]; } pk;
#pragma unroll
            for (int j = 0; j < 8; j++)
                pk.u[j] = __half_as_ushort(bb[(s8 + j) * 136 + nn]);
            size_t dst = ((size_t)(b2 * 16 + h2) * 64 + dk) * 2048 + ((bm * 128) & 2047) + s8;
            *(uint4*)&g_Vt[dst] = pk.q;
        }
    }
}

// ---------------- suffix tile sums of V ----------------
__global__ void __launch_bounds__(256) suffix_k() {
    __shared__ float pts[16][64];
    int bh = blockIdx.x, tid = threadIdx.x, dk = tid & 63, p = tid >> 6;
    for (int tt = 0; tt < 4; tt++) {
        int tt2 = p * 4 + tt;
        const __half* row = g_Vt + ((size_t)bh * 64 + dk) * 2048 + tt2 * 128;
        float s = 0.f;
        for (int j = 0; j < 128; j += 2) {
            float2 f = __half22float2(*(const __half2*)(row + j));
            s += f.x + f.y;
        }
        pts[tt2][dk] = s;
    }
    __syncthreads();
    if (tid < 64) {
        float run = 0.f;
        for (int tt = 15; tt >= 0; tt--) {
            g_Suf[((size_t)bh * 16 + tt) * 64 + tid] = run;
            run += pts[tt][tid];
        }
    }
}

// ---------------- head-axis softmax -> fp16 P (lower tiles only) ----------------
__global__ void __launch_bounds__(256) softmax_heads(const int* __restrict__ mask) {
    size_t e = ((size_t)blockIdx.x * 256 + threadIdx.x) * 4;
    int b = (int)(e >> 22);
    size_t r = e & (SSZ - 1);
    int q = (int)(r >> 11), k0 = (int)(r & 2047);
    if ((k0 >> 7) > (q >> 7)) return;   // upper tile: P never read
    int4 mk = *(const int4*)(mask + (size_t)q * 2048 + k0);
    int mks[4] = {mk.x, mk.y, mk.z, mk.w};
    float sv[16][4];
    if (mk.x | mk.y | mk.z | mk.w) {
#pragma unroll
        for (int h = 0; h < 16; h++)
            *(float4*)sv[h] = *(const float4*)(g_Scr + (size_t)(b * 16 + h) * SSZ + r);
    }
    ushort hs[16][4];
#pragma unroll
    for (int j = 0; j < 4; j++) {
        if (!mks[j]) {
#pragma unroll
            for (int h = 0; h < 16; h++) hs[h][j] = 0x2C00;  // 1/16 exact
        } else {
            float mx = -3.4e38f;
#pragma unroll
            for (int h = 0; h < 16; h++) mx = fmaxf(mx, sv[h][j]);
            float sum = 0.f, ev[16];
#pragma unroll
            for (int h = 0; h < 16; h++) { ev[h] = __expf(sv[h][j] - mx); sum += ev[h]; }
            float inv = 1.f / sum;
#pragma unroll
            for (int h = 0; h < 16; h++) hs[h][j] = __half_as_ushort(__float2half_rn(ev[h] * inv));
        }
    }
#pragma unroll
    for (int h = 0; h < 16; h++) {
        uint2 pk;
        pk.x = (uint32_t)hs[h][0] | ((uint32_t)hs[h][1] << 16);
        pk.y = (uint32_t)hs[h][2] | ((uint32_t)hs[h][3] << 16);
        *(uint2*)(g_P16 + (size_t)(b * 16 + h) * SSZ + r) = pk;
    }
}

// ---------------- launch ----------------
extern "C" void kernel_launch(void* const* d_in, const int* in_sizes, int n_in,
                              void* d_out, int out_size) {
    const float* q    = (const float*)d_in[0];
    const float* k    = (const float*)d_in[1];
    const float* v    = (const float*)d_in[2];
    const int*   mask = (const int*)  d_in[3];
    const float* wq_b = (const float*)d_in[5];
    const float* wk_b = (const float*)d_in[7];
    const float* wv_b = (const float*)d_in[9];
    const float* wo_b = (const float*)d_in[11];
    float* out = (float*)d_out;

    const int SM03 = 2 * (TILE + 128 * TPITCH);  // 73728
    const int SM4  = TILE + 128 * TPITCH;        // 36864 (NCH=1, single buffer used)
    const int SM5  = 2 * (TILE + 64 * TPITCH);   // 55296
    static bool attr_done = false;
    if (!attr_done) {
        cudaFuncSetAttribute(gemm_mma<0>, cudaFuncAttributeMaxDynamicSharedMemorySize, SM03);
        cudaFuncSetAttribute(gemm_mma<1>, cudaFuncAttributeMaxDynamicSharedMemorySize, SM03);
        cudaFuncSetAttribute(gemm_mma<2>, cudaFuncAttributeMaxDynamicSharedMemorySize, SM03);
        cudaFuncSetAttribute(gemm_mma<3>, cudaFuncAttributeMaxDynamicSharedMemorySize, SM03);
        cudaFuncSetAttribute(gemm_mma<4>, cudaFuncAttributeMaxDynamicSharedMemorySize, SM4);
        cudaFuncSetAttribute(gemm_mma<5>, cudaFuncAttributeMaxDynamicSharedMemorySize, SM5);
        attr_done = true;
    }

    cvt16<<<4096, 256>>>(q, 0);
    cvt16<<<4096, 256>>>(k, 1);
    cvt16<<<4096, 256>>>(v, 2);
    cvt16<<<1024, 256>>>((const float*)d_in[4], 3);
    cvt16<<<1024, 256>>>((const float*)d_in[6], 4);
    cvt16<<<1024, 256>>>((const float*)d_in[8], 5);
    cvt16<<<1024, 256>>>((const float*)d_in[10], 6);

    gemm_mma<0><<<dim3(8, 32, 1), 256, SM03>>>(wq_b, nullptr);
    gemm_mma<1><<<dim3(8, 32, 1), 256, SM03>>>(wk_b, nullptr);
    gemm_mma<2><<<dim3(8, 32, 1), 256, SM03>>>(wv_b, nullptr);

    suffix_k<<<32, 256>>>();

    gemm_mma<4><<<dim3(16, 16, 32), 256, SM4>>>(nullptr, nullptr);

    softmax_heads<<<8192, 256>>>(mask);

    gemm_mma<5><<<dim3(1, 16, 32), 256, SM5>>>(nullptr, nullptr);

    gemm_mma<3><<<dim3(8, 32, 1), 256, SM03>>>(wo_b, out);
}